// round 5
// baseline (speedup 1.0000x reference)
#include <cuda_runtime.h>
#include <math.h>

#define INPUT 40
#define HID   512
#define LAT   128
#define BATCH 1024
#define SEQ   512

#define RB   8          // batch rows per block
#define NTH  512        // threads per block
#define NBLK (BATCH/RB) // 128 blocks

typedef unsigned long long u64;

// ---------------- device scratch ----------------
// big cells (h, d1): gate-interleaved quad layout Wq[k][j*4+g], g in {i,f,g,o}
__device__ __align__(16) float g_WqiT_h [INPUT * 4*HID];
__device__ __align__(16) float g_WqhT_h [HID   * 4*HID];
__device__ __align__(16) float g_b_h    [4*HID];
__device__ __align__(16) float g_WqiT_d1[LAT * 4*HID];
__device__ __align__(16) float g_WqhT_d1[HID * 4*HID];
__device__ __align__(16) float g_b_d1   [4*HID];
// small cells: plain transposed WT[k][G]
__device__ __align__(16) float g_WiT_mu[HID * 4*LAT];
__device__ __align__(16) float g_WhT_mu[LAT * 4*LAT];
__device__ __align__(16) float g_b_mu  [4*LAT];
__device__ __align__(16) float g_WiT_lv[HID * 4*LAT];
__device__ __align__(16) float g_WhT_lv[LAT * 4*LAT];
__device__ __align__(16) float g_b_lv  [4*LAT];
__device__ __align__(16) float g_WiT_d2[HID   * 4*INPUT];
__device__ __align__(16) float g_WhT_d2[INPUT * 4*INPUT];
__device__ __align__(16) float g_b_d2  [4*INPUT];

// ---------------- prep ----------------
__device__ __forceinline__ void transpose_dev(const float* __restrict__ W,
                                              float* __restrict__ WT,
                                              int G, int K, int tid, int nt)
{
    int n = G * K;
    for (int i = tid; i < n; i += nt) {
        int k = i / G;
        int g = i - k * G;
        WT[i] = W[g * K + k];
    }
}

// Wq[k*(4*HID) + j*4 + g] = W[(g*HID + j)*K + k]
__device__ __forceinline__ void make_quad(const float* __restrict__ W,
                                          float* __restrict__ Wq,
                                          int K, int tid, int nt)
{
    int n = K * 4 * HID;
    for (int i = tid; i < n; i += nt) {
        int k   = i / (4 * HID);
        int col = i - k * 4 * HID;
        int j   = col >> 2;
        int g   = col & 3;
        Wq[i] = W[(g * HID + j) * K + k];
    }
}

__global__ void prep_kernel(
    const float* Wih_h,  const float* Whh_h,  const float* bih_h,  const float* bhh_h,
    const float* Wih_mu, const float* Whh_mu, const float* bih_mu, const float* bhh_mu,
    const float* Wih_lv, const float* Whh_lv, const float* bih_lv, const float* bhh_lv,
    const float* Wih_d1, const float* Whh_d1, const float* bih_d1, const float* bhh_d1,
    const float* Wih_d2, const float* Whh_d2, const float* bih_d2, const float* bhh_d2)
{
    int tid = blockIdx.x * blockDim.x + threadIdx.x;
    int nt  = gridDim.x * blockDim.x;

    make_quad(Wih_h,  g_WqiT_h,  INPUT, tid, nt);
    make_quad(Whh_h,  g_WqhT_h,  HID,   tid, nt);
    make_quad(Wih_d1, g_WqiT_d1, LAT,   tid, nt);
    make_quad(Whh_d1, g_WqhT_d1, HID,   tid, nt);

    transpose_dev(Wih_mu, g_WiT_mu, 4*LAT, HID,   tid, nt);
    transpose_dev(Whh_mu, g_WhT_mu, 4*LAT, LAT,   tid, nt);
    transpose_dev(Wih_lv, g_WiT_lv, 4*LAT, HID,   tid, nt);
    transpose_dev(Whh_lv, g_WhT_lv, 4*LAT, LAT,   tid, nt);
    transpose_dev(Wih_d2, g_WiT_d2, 4*INPUT, HID,   tid, nt);
    transpose_dev(Whh_d2, g_WhT_d2, 4*INPUT, INPUT, tid, nt);

    for (int i = tid; i < 4*HID;   i += nt) g_b_h[i]  = bih_h[i]  + bhh_h[i];
    for (int i = tid; i < 4*LAT;   i += nt) g_b_mu[i] = bih_mu[i] + bhh_mu[i];
    for (int i = tid; i < 4*LAT;   i += nt) g_b_lv[i] = bih_lv[i] + bhh_lv[i];
    for (int i = tid; i < 4*HID;   i += nt) g_b_d1[i] = bih_d1[i] + bhh_d1[i];
    for (int i = tid; i < 4*INPUT; i += nt) g_b_d2[i] = bih_d2[i] + bhh_d2[i];
}

// ---------------- fast activations (1 MUFU each) ----------------
__device__ __forceinline__ float tanh_fast(float x)
{
    float y;
    asm("tanh.approx.f32 %0, %1;" : "=f"(y) : "f"(x));
    return y;
}
__device__ __forceinline__ float sigf(float x)
{
    return fmaf(tanh_fast(0.5f * x), 0.5f, 0.5f);
}

// ---------------- packed f32x2 helpers ----------------
__device__ __forceinline__ void ffma2(u64& d, u64 a, u64 b)
{
    asm("fma.rn.f32x2 %0, %1, %2, %0;" : "+l"(d) : "l"(a), "l"(b));
}
__device__ __forceinline__ u64 pack2(float lo, float hi)
{
    u64 r;
    asm("mov.b64 %0, {%1, %2};" : "=l"(r) : "f"(lo), "f"(hi));
    return r;
}
__device__ __forceinline__ void unpack2(u64 v, float& lo, float& hi)
{
    asm("mov.b64 {%0, %1}, %2;" : "=f"(lo), "=f"(hi) : "l"(v));
}
__device__ __forceinline__ u64 add2(u64 a, u64 b)
{
    u64 d;
    asm("add.rn.f32x2 %0, %1, %2;" : "=l"(d) : "l"(a), "l"(b));
    return d;
}
__device__ __forceinline__ u64 shfl_xor1_u64(u64 v)
{
    unsigned lo = (unsigned)v, hi = (unsigned)(v >> 32);
    lo = __shfl_xor_sync(0xffffffffu, lo, 1);
    hi = __shfl_xor_sync(0xffffffffu, hi, 1);
    return ((u64)hi << 32) | lo;
}

// ---------------- big-cell GEMM: quad gates per unit, 2k per iter ----------------
template<int K>
__device__ __forceinline__ void accum_quad(const u64* __restrict__ aDup,   // smem dup, u64 idx r*K+k
                                           const float* __restrict__ Wq,   // gmem [K][4*HID]
                                           int j4, u64 (&accIF)[RB], u64 (&accGO)[RB])
{
    #pragma unroll 2
    for (int k = 0; k < K; k += 2) {
        ulonglong2 a2[RB];
        #pragma unroll
        for (int r = 0; r < RB; r++)
            a2[r] = *reinterpret_cast<const ulonglong2*>(aDup + r * K + k);  // LDS.128: (ak,ak),(ak1,ak1)

        ulonglong2 w0 = *reinterpret_cast<const ulonglong2*>(Wq + (size_t)k * (4*HID) + j4);
        ulonglong2 w1 = *reinterpret_cast<const ulonglong2*>(Wq + (size_t)(k+1) * (4*HID) + j4);

        #pragma unroll
        for (int r = 0; r < RB; r++) {
            ffma2(accIF[r], a2[r].x, w0.x);
            ffma2(accGO[r], a2[r].x, w0.y);
        }
        #pragma unroll
        for (int r = 0; r < RB; r++) {
            ffma2(accIF[r], a2[r].y, w1.x);
            ffma2(accGO[r], a2[r].y, w1.y);
        }
    }
}

// ---------------- small-cell GEMM: 4 gates (2 pairs) per thread, runtime k range ----------------
__device__ __forceinline__ void accum2_rt(const u64* __restrict__ aDup, int K,
                                          int k0, int k1,
                                          const float* __restrict__ WT, int G, int g0,
                                          u64 (&acc)[2][RB])
{
    #pragma unroll 2
    for (int k = k0; k < k1; k += 2) {
        ulonglong2 a2[RB];
        #pragma unroll
        for (int r = 0; r < RB; r++)
            a2[r] = *reinterpret_cast<const ulonglong2*>(aDup + r * K + k);

        ulonglong2 w0 = *reinterpret_cast<const ulonglong2*>(WT + (size_t)k * G + g0);
        ulonglong2 w1 = *reinterpret_cast<const ulonglong2*>(WT + (size_t)(k+1) * G + g0);

        #pragma unroll
        for (int r = 0; r < RB; r++) {
            ffma2(acc[0][r], a2[r].x, w0.x);
            ffma2(acc[1][r], a2[r].x, w0.y);
        }
        #pragma unroll
        for (int r = 0; r < RB; r++) {
            ffma2(acc[0][r], a2[r].y, w1.x);
            ffma2(acc[1][r], a2[r].y, w1.y);
        }
    }
}

// d2 helper (gate-pair, scalar k, runtime range)
template<int NGP>
__device__ __forceinline__ void accum_pairs_rt(const u64* __restrict__ aDup, int K,
                                               int k0, int k1,
                                               const float* __restrict__ WT,
                                               int G, int g0, u64 (&acc)[NGP][RB])
{
    #pragma unroll 4
    for (int k = k0; k < k1; k++) {
        u64 a[RB];
        #pragma unroll
        for (int r = 0; r < RB; r++) a[r] = aDup[r * K + k];
        const u64* w = reinterpret_cast<const u64*>(WT + (size_t)k * G + g0);
        u64 wv[NGP];
        #pragma unroll
        for (int i = 0; i < NGP; i++) wv[i] = w[i];
        #pragma unroll
        for (int i = 0; i < NGP; i++)
            #pragma unroll
            for (int r = 0; r < RB; r++)
                ffma2(acc[i][r], a[r], wv[i]);
    }
}

// ---------------- elementwise LSTM update (small cells) ----------------
template<int G, int H>
__device__ __forceinline__ void elem_lstm(const float* __restrict__ gatesT,
                                          float* __restrict__ hDup,
                                          float* __restrict__ cT,
                                          float* __restrict__ outG, size_t rs,
                                          int lt, int nthr)
{
    for (int idx = lt; idx < H * RB; idx += nthr) {
        const int r = idx / H;
        const int j = idx - r * H;
        const float* gr = gatesT + r * G;
        float xi = gr[j];
        float xf = gr[j + H];
        float xg = gr[j + 2 * H];
        float xo = gr[j + 3 * H];
        float c = sigf(xf) * cT[idx] + sigf(xi) * tanh_fast(xg);
        float h = sigf(xo) * tanh_fast(c);
        cT[idx] = c;
        reinterpret_cast<u64*>(hDup)[idx] = pack2(h, h);
        if (outG) outG[rs * r + j] = h;
    }
}

// ---------------- main persistent kernel ----------------
extern __shared__ float smem[];

__global__ void __launch_bounds__(NTH, 1) vae_kernel(
    const float* __restrict__ x,     // [B][S][INPUT]
    const float* __restrict__ eps,   // [B][S][LAT]
    float* __restrict__ out)         // recon ++ mu ++ logvar
{
    // smem layout (floats)
    float* gates = smem;                         // 2*RB*4*LAT = 8192 (mu+lv gates / d2 partials)
    float* hDup  = gates + 2 * RB * 4 * LAT;     // RB*HID*2 = 8192
    float* hmDup = hDup + RB * HID * 2;          // 2048
    float* cmT   = hmDup + RB * LAT * 2;         // 1024
    float* hlDup = cmT + RB * LAT;               // 2048
    float* clT   = hlDup + RB * LAT * 2;         // 1024
    float* h2Dup = clT + RB * LAT;               // 640
    float* c2T   = h2Dup + RB * INPUT * 2;       // 320
    float* xzA   = c2T + RB * INPUT;             // 2048
    float* xzB   = xzA + RB * LAT * 2;           // 2048

    const int t  = threadIdx.x;
    const int r0 = blockIdx.x * RB;

    float* reconO = out;
    float* muO    = out + (size_t)BATCH * SEQ * INPUT;
    float* lvO    = muO + (size_t)BATCH * SEQ * LAT;

    // staging / d2 index helpers
    const int exr = (t < INPUT * RB) ? t / INPUT : 0;
    const int exk = (t < INPUT * RB) ? t - exr * INPUT : 0;

    // mu/lv phase mapping: 512 threads = 2 cells x 128 gate-quads x 2 K-chunks (even/odd lane)
    const int cellsel = (t >= 256);
    const int tt      = t & 255;
    const int p       = tt >> 1;        // gate-quad index 0..127
    const int kchunk  = tt & 1;         // 0: K[0,320)  1: K[320,512)+hm[0,128)
    const int g0s     = p * 4;

    float cReg[RB];                      // big-cell c state, unit j = t

    // ---- zero encoder state ----
    #pragma unroll
    for (int r = 0; r < RB; r++) cReg[r] = 0.f;
    for (int i = t; i < HID * RB; i += NTH) reinterpret_cast<u64*>(hDup)[i] = 0ull;
    for (int i = t; i < LAT * RB; i += NTH) {
        reinterpret_cast<u64*>(hmDup)[i] = 0ull; cmT[i] = 0.f;
        reinterpret_cast<u64*>(hlDup)[i] = 0ull; clT[i] = 0.f;
    }
    // stage x_0
    if (t < INPUT * RB) {
        float v = x[((size_t)(r0 + exr) * SEQ + 0) * INPUT + exk];
        reinterpret_cast<u64*>(xzA)[exr * INPUT + exk] = pack2(v, v);
    }
    __syncthreads();

    const int j4 = t * 4;

    // ================= encoder =================
    for (int s = 0; s < SEQ; s++) {
        float* xzCur = (s & 1) ? xzB : xzA;
        float* xzNxt = (s & 1) ? xzA : xzB;

        // ---- P0: h-cell GEMM (unit j = t), epilogue in regs ----
        float hNew[RB];
        {
            u64 accIF[RB], accGO[RB];
            u64 bIF = pack2(g_b_h[t], g_b_h[HID + t]);
            u64 bGO = pack2(g_b_h[2*HID + t], g_b_h[3*HID + t]);
            #pragma unroll
            for (int r = 0; r < RB; r++) { accIF[r] = bIF; accGO[r] = bGO; }

            accum_quad<INPUT>((const u64*)xzCur, g_WqiT_h, j4, accIF, accGO);
            accum_quad<HID>  ((const u64*)hDup,  g_WqhT_h, j4, accIF, accGO);

            #pragma unroll
            for (int r = 0; r < RB; r++) {
                float xi, xf, xg, xo;
                unpack2(accIF[r], xi, xf);
                unpack2(accGO[r], xg, xo);
                float c = sigf(xf) * cReg[r] + sigf(xi) * tanh_fast(xg);
                float h = sigf(xo) * tanh_fast(c);
                cReg[r] = c;
                hNew[r] = h;
            }
        }
        __syncthreads();   // all threads done reading hDup_old

        // ---- P1: publish h, stage x_{s+1} ----
        #pragma unroll
        for (int r = 0; r < RB; r++)
            reinterpret_cast<u64*>(hDup)[r * HID + t] = pack2(hNew[r], hNew[r]);
        if (s + 1 < SEQ && t < INPUT * RB) {
            float v = x[((size_t)(r0 + exr) * SEQ + (s + 1)) * INPUT + exk];
            reinterpret_cast<u64*>(xzNxt)[exr * INPUT + exk] = pack2(v, v);
        }
        __syncthreads();

        // ---- P2: mu & lv GEMM (K-split even/odd lanes, shfl combine) ----
        {
            const float* Wi = cellsel ? g_WiT_lv : g_WiT_mu;
            const float* Wh = cellsel ? g_WhT_lv : g_WhT_mu;
            const float* bb = cellsel ? g_b_lv   : g_b_mu;
            const u64* hsml = cellsel ? (const u64*)hlDup : (const u64*)hmDup;

            u64 acc[2][RB];
            if (kchunk == 0) {
                u64 b0 = pack2(bb[g0s], bb[g0s + 1]);
                u64 b1 = pack2(bb[g0s + 2], bb[g0s + 3]);
                #pragma unroll
                for (int r = 0; r < RB; r++) { acc[0][r] = b0; acc[1][r] = b1; }
                accum2_rt((const u64*)hDup, HID, 0, 320, Wi, 4*LAT, g0s, acc);
            } else {
                #pragma unroll
                for (int r = 0; r < RB; r++) { acc[0][r] = 0ull; acc[1][r] = 0ull; }
                accum2_rt((const u64*)hDup, HID, 320, HID, Wi, 4*LAT, g0s, acc);
                accum2_rt(hsml,             LAT, 0,   LAT, Wh, 4*LAT, g0s, acc);
            }
            // combine partials across lane pair
            #pragma unroll
            for (int i = 0; i < 2; i++)
                #pragma unroll
                for (int r = 0; r < RB; r++)
                    acc[i][r] = add2(acc[i][r], shfl_xor1_u64(acc[i][r]));

            if (kchunk == 0) {
                u64* gcell = reinterpret_cast<u64*>(gates + cellsel * RB * 4 * LAT);
                #pragma unroll
                for (int r = 0; r < RB; r++) {
                    gcell[r * (2 * LAT) + 2 * p]     = acc[0][r];
                    gcell[r * (2 * LAT) + 2 * p + 1] = acc[1][r];
                }
            }
        }
        __syncthreads();

        // ---- P3: mu/lv elementwise ----
        if (t < 256)
            elem_lstm<4*LAT, LAT>(gates, hmDup, cmT,
                                  muO + ((size_t)r0 * SEQ + s) * LAT, (size_t)SEQ * LAT,
                                  t, 256);
        else
            elem_lstm<4*LAT, LAT>(gates + RB * 4 * LAT, hlDup, clT,
                                  lvO + ((size_t)r0 * SEQ + s) * LAT, (size_t)SEQ * LAT,
                                  t - 256, 256);
        __syncthreads();
    }

    // ---- reset for decoder ----
    #pragma unroll
    for (int r = 0; r < RB; r++) cReg[r] = 0.f;
    for (int i = t; i < HID * RB; i += NTH) reinterpret_cast<u64*>(hDup)[i] = 0ull;
    for (int i = t; i < INPUT * RB; i += NTH) { reinterpret_cast<u64*>(h2Dup)[i] = 0ull; c2T[i] = 0.f; }
    // stage z_0  (LAT*RB = 1024 elements > NTH: grid-stride loop!)
    for (int idx = t; idx < LAT * RB; idx += NTH) {
        int r = idx >> 7, k = idx & (LAT - 1);
        size_t off = ((size_t)(r0 + r) * SEQ + 0) * LAT + k;
        float v = fmaf(eps[off], __expf(0.5f * lvO[off]), muO[off]);
        reinterpret_cast<u64*>(xzA)[idx] = pack2(v, v);
    }
    __syncthreads();

    // ================= decoder =================
    for (int s = 0; s < SEQ; s++) {
        float* xzCur = (s & 1) ? xzB : xzA;
        float* xzNxt = (s & 1) ? xzA : xzB;

        // ---- P0: d1 GEMM + epilogue ----
        float hNew[RB];
        {
            u64 accIF[RB], accGO[RB];
            u64 bIF = pack2(g_b_d1[t], g_b_d1[HID + t]);
            u64 bGO = pack2(g_b_d1[2*HID + t], g_b_d1[3*HID + t]);
            #pragma unroll
            for (int r = 0; r < RB; r++) { accIF[r] = bIF; accGO[r] = bGO; }

            accum_quad<LAT>((const u64*)xzCur, g_WqiT_d1, j4, accIF, accGO);
            accum_quad<HID>((const u64*)hDup,  g_WqhT_d1, j4, accIF, accGO);

            #pragma unroll
            for (int r = 0; r < RB; r++) {
                float xi, xf, xg, xo;
                unpack2(accIF[r], xi, xf);
                unpack2(accGO[r], xg, xo);
                float c = sigf(xf) * cReg[r] + sigf(xi) * tanh_fast(xg);
                float h = sigf(xo) * tanh_fast(c);
                cReg[r] = c;
                hNew[r] = h;
            }
        }
        __syncthreads();

        // ---- P1: publish h1, stage z_{s+1} (grid-stride: 1024 elems, 512 threads) ----
        #pragma unroll
        for (int r = 0; r < RB; r++)
            reinterpret_cast<u64*>(hDup)[r * HID + t] = pack2(hNew[r], hNew[r]);
        if (s + 1 < SEQ) {
            for (int idx = t; idx < LAT * RB; idx += NTH) {
                int r = idx >> 7, k = idx & (LAT - 1);
                size_t off = ((size_t)(r0 + r) * SEQ + (s + 1)) * LAT + k;
                float v = fmaf(eps[off], __expf(0.5f * lvO[off]), muO[off]);
                reinterpret_cast<u64*>(xzNxt)[idx] = pack2(v, v);
            }
        }
        __syncthreads();

        // ---- P2: d2 GEMM (K-split across two 80-thread groups) ----
        {
            constexpr int G2 = 4 * INPUT;   // 160
            float* gA = gates;
            float* gB = gates + RB * G2;
            if (t < 80) {
                const int g0 = t * 2;
                u64 acc[1][RB];
                u64 bb = pack2(g_b_d2[g0], g_b_d2[g0 + 1]);
                #pragma unroll
                for (int r = 0; r < RB; r++) acc[0][r] = bb;
                accum_pairs_rt<1>((const u64*)hDup, HID, 0, 256, g_WiT_d2, G2, g0, acc);
                #pragma unroll
                for (int r = 0; r < RB; r++)
                    *reinterpret_cast<u64*>(&gA[r * G2 + g0]) = acc[0][r];
            } else if (t >= 256 && t < 336) {
                const int g0 = (t - 256) * 2;
                u64 acc[1][RB];
                #pragma unroll
                for (int r = 0; r < RB; r++) acc[0][r] = 0ull;
                accum_pairs_rt<1>((const u64*)hDup,  HID,   256, HID,   g_WiT_d2, G2, g0, acc);
                accum_pairs_rt<1>((const u64*)h2Dup, INPUT, 0,   INPUT, g_WhT_d2, G2, g0, acc);
                #pragma unroll
                for (int r = 0; r < RB; r++)
                    *reinterpret_cast<u64*>(&gB[r * G2 + g0]) = acc[0][r];
            }
        }
        __syncthreads();

        // ---- P3: d2 elementwise ----
        if (t < INPUT * RB) {
            constexpr int G2 = 4 * INPUT;
            const float* gA = gates + exr * G2;
            const float* gB = gates + RB * G2 + exr * G2;
            const int j = exk;
            float xi = gA[j]             + gB[j];
            float xf = gA[j + INPUT]     + gB[j + INPUT];
            float xg = gA[j + 2 * INPUT] + gB[j + 2 * INPUT];
            float xo = gA[j + 3 * INPUT] + gB[j + 3 * INPUT];
            const int idx = exr * INPUT + j;
            float c = sigf(xf) * c2T[idx] + sigf(xi) * tanh_fast(xg);
            float h = sigf(xo) * tanh_fast(c);
            c2T[idx] = c;
            reinterpret_cast<u64*>(h2Dup)[idx] = pack2(h, h);
            reconO[((size_t)(r0 + exr) * SEQ + s) * INPUT + j] = h;
        }
        __syncthreads();
    }
}

// ---------------- launcher ----------------
extern "C" void kernel_launch(void* const* d_in, const int* in_sizes, int n_in,
                              void* d_out, int out_size)
{
    (void)in_sizes; (void)n_in; (void)out_size;

    const float* x   = (const float*)d_in[0];
    const float* eps = (const float*)d_in[1];

    prep_kernel<<<512, 256>>>(
        (const float*)d_in[2],  (const float*)d_in[3],  (const float*)d_in[4],  (const float*)d_in[5],
        (const float*)d_in[6],  (const float*)d_in[7],  (const float*)d_in[8],  (const float*)d_in[9],
        (const float*)d_in[10], (const float*)d_in[11], (const float*)d_in[12], (const float*)d_in[13],
        (const float*)d_in[14], (const float*)d_in[15], (const float*)d_in[16], (const float*)d_in[17],
        (const float*)d_in[18], (const float*)d_in[19], (const float*)d_in[20], (const float*)d_in[21]);

    const int SMEM_FLOATS = 2*RB*4*LAT          // gates / partials
                          + RB*HID*2            // hDup
                          + RB*LAT*2 + RB*LAT   // hmDup, cmT
                          + RB*LAT*2 + RB*LAT   // hlDup, clT
                          + RB*INPUT*2 + RB*INPUT // h2Dup, c2T
                          + 2 * RB*LAT*2;       // xzA, xzB
    const int SMEM_BYTES = SMEM_FLOATS * (int)sizeof(float);
    cudaFuncSetAttribute(vae_kernel, cudaFuncAttributeMaxDynamicSharedMemorySize, SMEM_BYTES);

    vae_kernel<<<NBLK, NTH, SMEM_BYTES>>>(x, eps, (float*)d_out);
}